// round 16
// baseline (speedup 1.0000x reference)
#include <cuda_runtime.h>
#include <cuda_bf16.h>

// RFCM loss, fused single-pass, separable + z-adjoint, f32x2 packed,
// cp.async 3-stage plane pipeline (register-free latency hiding).
//   mem = y_pred^2
//   J1 total = sum_{b,k} (A - B^2/C),  A=Σ mem*img^2, B=Σ mem*img, C=Σ mem
//   J2 = Σ_z [ BS(z)·M3S(z) − MS(z)² − Σ_k b_k(z)·m3_k(z) + Σ_k m_k(z)² ]
//     b_k = 2D 3x3 box at plane z, m3_k(z) = m_k(z−1)+m_k(z)+m_k(z+1)
//   out = (ΣJ1 + 8e-4·ΣJ2) / (B*N)
//
// Raw y_pred planes (4 clusters × 10 rows: 8 center + 2 y-halo) stream into a
// 3-stage smem ring via cp.async.cg (zfill for y OOB). Each warp consumes its
// 3 y-rows with LDS.128, squares (f32x2), y-sums first, then one x 3-tap via
// 2 shuffles per cluster -> 2D box. No STS, no rowsum exchange, 1 barrier per
// plane, ~2 planes of async slack. z-halo planes via plain LDG centers().
// Deterministic last-block finalize.

namespace {
constexpr int TY   = 8;
constexpr int CZ   = 16;
constexpr int NTH  = 32 * TY;         // 256
constexpr int NVOX = 128 * 128 * 128;
constexpr int PL   = 128 * 128;       // z-plane stride (floats)
constexpr int GYB  = 128 / TY;        // 16
constexpr int GZB  = 128 / CZ;        // 8
constexpr int NBLK = GYB * GZB * 2;   // 256
constexpr int SROW = TY + 2;          // 10 rows per cluster per stage
constexpr int STG  = 4 * SROW * 128;  // floats per stage = 5120 (20 KB)
constexpr int NS   = 3;               // pipeline stages
constexpr int SMEM_BYTES = NS * STG * 4;  // 61440
}

__device__ float g_part[NBLK * 13];
__device__ unsigned int g_count;      // zero-init; reset by finalizer each launch

// ---- packed f32x2 helpers (sm_103a FFMA2 path; PTX-only) ----
struct P2 { unsigned long long v; };
struct Q  { P2 a, b; };               // a = lanes (0,1), b = lanes (2,3)

__device__ __forceinline__ P2 pk(float lo, float hi) {
    P2 r; asm("mov.b64 %0, {%1, %2};" : "=l"(r.v) : "f"(lo), "f"(hi)); return r;
}
__device__ __forceinline__ void upk(P2 a, float& lo, float& hi) {
    asm("mov.b64 {%0, %1}, %2;" : "=f"(lo), "=f"(hi) : "l"(a.v));
}
__device__ __forceinline__ P2 padd(P2 a, P2 b) {
    P2 r; asm("add.rn.f32x2 %0, %1, %2;" : "=l"(r.v) : "l"(a.v), "l"(b.v)); return r;
}
__device__ __forceinline__ P2 pmul(P2 a, P2 b) {
    P2 r; asm("mul.rn.f32x2 %0, %1, %2;" : "=l"(r.v) : "l"(a.v), "l"(b.v)); return r;
}
__device__ __forceinline__ P2 pfma(P2 a, P2 b, P2 c) {
    P2 r; asm("fma.rn.f32x2 %0, %1, %2, %3;"
              : "=l"(r.v) : "l"(a.v), "l"(b.v), "l"(c.v)); return r;
}
__device__ __forceinline__ P2 pneg(P2 a) {
    P2 r; asm("xor.b64 %0, %1, 0x8000000080000000;" : "=l"(r.v) : "l"(a.v)); return r;
}
__device__ __forceinline__ P2 pzero() { P2 r; r.v = 0ull; return r; }
__device__ __forceinline__ float psum(P2 a) { float lo, hi; upk(a, lo, hi); return lo + hi; }
__device__ __forceinline__ P2 u2a(ulonglong2 u) { P2 r; r.v = u.x; return r; }
__device__ __forceinline__ P2 u2b(ulonglong2 u) { P2 r; r.v = u.y; return r; }

__device__ __forceinline__ void cpa16(unsigned dst, const void* src, int nbytes) {
    asm volatile("cp.async.cg.shared.global [%0], [%1], 16, %2;"
                 :: "r"(dst), "l"(src), "r"(nbytes) : "memory");
}
__device__ __forceinline__ void cpa_commit() {
    asm volatile("cp.async.commit_group;" ::: "memory");
}
template <int N> __device__ __forceinline__ void cpa_wait() {
    asm volatile("cp.async.wait_group %0;" :: "n"(N) : "memory");
}

__global__ void __launch_bounds__(NTH, 2)
rfcm(const float* __restrict__ yp, const float* __restrict__ img,
     float* __restrict__ out) {
    extern __shared__ __align__(16) float sm[];   // NS stages of raw planes
    __shared__ unsigned amLast;
    const int lane = threadIdx.x, wy = threadIdx.y;
    const int tid  = wy * 32 + lane;
    const int gy0  = blockIdx.x * TY;
    const int z0   = blockIdx.y * CZ;
    const int b    = blockIdx.z;
    const int x0   = lane * 4;

    const float* ypb = yp  + (size_t)b * 4 * NVOX;
    const float* pc[4];
    #pragma unroll
    for (int k = 0; k < 4; ++k)
        pc[k] = ypb + (size_t)k * NVOX + (size_t)(gy0 + wy) * 128 + x0;
    const float* pim = img + (size_t)b * NVOX + (size_t)(gy0 + wy) * 128 + x0;

    // cp.async unit setup: 40 row-units (4 clusters × 10 rows) = 8 warps × 5
    const unsigned sbase = (unsigned)__cvta_generic_to_shared(sm);
    const float* gsrc[5]; unsigned doff[5]; int ssz[5];
    #pragma unroll
    for (int j = 0; j < 5; ++j) {
        int u = wy + 8 * j;            // 0..39
        int k = u / SROW, r = u - k * SROW;
        int y = gy0 - 1 + r;
        bool yin = ((unsigned)y < 128u);
        gsrc[j] = ypb + (size_t)k * NVOX + (size_t)(yin ? y : 0) * 128 + lane * 4;
        doff[j] = (unsigned)(((k * SROW + r) * 128 + lane * 4) * 4);
        ssz[j]  = yin ? 16 : 0;        // zero-fill y-halo OOB
    }
    auto issue = [&](int zp, int s) {  // zp always in [0,128)
        const unsigned st = sbase + (unsigned)(s * STG * 4);
        #pragma unroll
        for (int j = 0; j < 5; ++j)
            cpa16(st + doff[j], gsrc[j] + (size_t)zp * PL, ssz[j]);
    };
    auto centers = [&](int zp, Q m[4]) {   // z-halo plane: center memberships only
        const bool zin = ((unsigned)zp < 128u);
        #pragma unroll
        for (int k = 0; k < 4; ++k) {
            float4 u = zin ? __ldg(reinterpret_cast<const float4*>(pc[k] + (size_t)zp * PL))
                           : make_float4(0.f, 0.f, 0.f, 0.f);
            m[k].a = pk(u.x * u.x, u.y * u.y);
            m[k].b = pk(u.z * u.z, u.w * u.w);
        }
    };
    auto ldimg = [&](int zp) -> Q {
        ulonglong2 u = __ldg(reinterpret_cast<const ulonglong2*>(pim + (size_t)zp * PL));
        Q q; q.a = u2a(u); q.b = u2b(u); return q;
    };
    // consume stage s: per cluster read 3 y-rows, square, y-sum, x 3-tap
    auto consume = [&](int s, Q box[4], Q m[4]) {
        const float* st = sm + s * STG;
        #pragma unroll
        for (int k = 0; k < 4; ++k) {
            const float* rp = st + (k * SROW + wy) * 128 + x0;
            ulonglong2 u0 = *reinterpret_cast<const ulonglong2*>(rp);
            ulonglong2 u1 = *reinterpret_cast<const ulonglong2*>(rp + 128);
            ulonglong2 u2 = *reinterpret_cast<const ulonglong2*>(rp + 256);
            P2 s1a = pmul(u2a(u1), u2a(u1)), s1b = pmul(u2b(u1), u2b(u1));
            m[k].a = s1a; m[k].b = s1b;
            P2 ya = padd(padd(pmul(u2a(u0), u2a(u0)), s1a), pmul(u2a(u2), u2a(u2)));
            P2 yb = padd(padd(pmul(u2b(u0), u2b(u0)), s1b), pmul(u2b(u2), u2b(u2)));
            float yx, yy, yz, yw;
            upk(ya, yx, yy); upk(yb, yz, yw);
            float left  = __shfl_up_sync(0xffffffffu, yw, 1);
            float right = __shfl_down_sync(0xffffffffu, yx, 1);
            if (lane == 0)  left  = 0.f;
            if (lane == 31) right = 0.f;
            float t1 = yx + yy, t2 = yz + yw;
            box[k].a = pk(left + t1, t1 + yz);
            box[k].b = pk(yy + t2, t2 + right);
        }
    };

    Q m1[4], m2[4], bprev[4], mhalo[4];
    #pragma unroll
    for (int k = 0; k < 4; ++k) {
        m1[k].a = pzero(); m1[k].b = pzero();
        bprev[k].a = pzero(); bprev[k].b = pzero();
    }
    P2 A2[4], B2[4], C2[4];
    #pragma unroll
    for (int k = 0; k < 4; ++k) { A2[k] = pzero(); B2[k] = pzero(); C2[k] = pzero(); }
    P2 j2a = pzero(), j2b = pzero();

    auto j2step = [&](const Q mnext[4]) {  // J2 at z: bprev=b(z), m2=m(z), m1=m(z-1)
        P2 M3a = pzero(), M3b = pzero(), BSa = pzero(), BSb = pzero();
        P2 MSa = pzero(), MSb = pzero();
        P2 t1a = pzero(), t1b = pzero(), t2a = pzero(), t2b = pzero();
        #pragma unroll
        for (int k = 0; k < 4; ++k) {
            P2 m3a = padd(padd(m1[k].a, m2[k].a), mnext[k].a);
            P2 m3b = padd(padd(m1[k].b, m2[k].b), mnext[k].b);
            M3a = padd(M3a, m3a);          M3b = padd(M3b, m3b);
            BSa = padd(BSa, bprev[k].a);   BSb = padd(BSb, bprev[k].b);
            MSa = padd(MSa, m2[k].a);      MSb = padd(MSb, m2[k].b);
            t1a = pfma(bprev[k].a, m3a, t1a); t1b = pfma(bprev[k].b, m3b, t1b);
            t2a = pfma(m2[k].a, m2[k].a, t2a); t2b = pfma(m2[k].b, m2[k].b, t2b);
        }
        j2a = pfma(BSa, M3a, j2a); j2a = pfma(pneg(MSa), MSa, j2a);
        j2a = padd(j2a, padd(t2a, pneg(t1a)));
        j2b = pfma(BSb, M3b, j2b); j2b = pfma(pneg(MSb), MSb, j2b);
        j2b = padd(j2b, padd(t2b, pneg(t1b)));
    };

    // prologue: centers(z0-1), prime 2 pipeline stages, prefetch img(z0)
    centers(z0 - 1, m2);              // m2 = m(z0-1)
    issue(z0, 0);     cpa_commit();
    issue(z0 + 1, 1); cpa_commit();
    Q imgc = ldimg(z0);
    Q imgn; imgn.a = pzero(); imgn.b = pzero();

    #pragma unroll
    for (int i = 0; i < CZ; ++i) {    // p = z0 + i : plane being consumed
        cpa_wait<1>();                // plane p's group complete (p+1 in flight)
        __syncthreads();              // all warps' units landed; stage (i+2)%3 free
        if (i + 2 < CZ) issue(z0 + i + 2, (i + 2) % NS);
        cpa_commit();                 // keep group count uniform (may be empty)

        Q bnew[4], mnew[4];
        consume(i % NS, bnew, mnew);
        if (i < CZ - 1) imgn = ldimg(z0 + i + 1);
        else            centers(z0 + CZ, mhalo);

        {                             // ABC at plane p
            P2 i2a = pmul(imgc.a, imgc.a), i2b = pmul(imgc.b, imgc.b);
            #pragma unroll
            for (int k = 0; k < 4; ++k) {
                C2[k] = padd(C2[k], padd(mnew[k].a, mnew[k].b));
                B2[k] = pfma(mnew[k].a, imgc.a, pfma(mnew[k].b, imgc.b, B2[k]));
                A2[k] = pfma(mnew[k].a, i2a,    pfma(mnew[k].b, i2b,    A2[k]));
            }
        }
        if (i > 0) j2step(mnew);      // J2 at z = p-1
        #pragma unroll
        for (int k = 0; k < 4; ++k) { bprev[k] = bnew[k]; m1[k] = m2[k]; m2[k] = mnew[k]; }
        imgc = imgn;
    }
    j2step(mhalo);                    // J2 at z0+CZ-1 (needs m(z0+CZ) centers)
    cpa_wait<0>();                    // drain (tail groups are empty)

    // ---- block reduction: 13 scalars ----
    float vals[13];
    #pragma unroll
    for (int k = 0; k < 4; ++k) {
        vals[k]     = psum(A2[k]);
        vals[4 + k] = psum(B2[k]);
        vals[8 + k] = psum(C2[k]);
    }
    vals[12] = psum(j2a) + psum(j2b);
    #pragma unroll
    for (int off = 16; off; off >>= 1)
        #pragma unroll
        for (int j = 0; j < 13; ++j)
            vals[j] += __shfl_down_sync(0xffffffffu, vals[j], off);

    __syncthreads();                       // stage smem done; reuse as scratch
    float* red = sm;
    if (lane == 0) {
        #pragma unroll
        for (int j = 0; j < 13; ++j) red[wy * 13 + j] = vals[j];
    }
    __syncthreads();
    const int blockid = blockIdx.x + GYB * blockIdx.y + (GYB * GZB) * blockIdx.z;
    if (tid < 13) {
        float s = 0.f;
        #pragma unroll
        for (int w = 0; w < TY; ++w) s += red[w * 13 + tid];
        g_part[blockid * 13 + tid] = s;
    }

    // ---- deterministic last-block finalize ----
    __threadfence();
    if (tid == 0) amLast = (atomicAdd(&g_count, 1u) == (unsigned)(NBLK - 1)) ? 1u : 0u;
    __syncthreads();
    if (amLast) {
        __threadfence();                   // acquire all g_part writes
        if (tid == 0) g_count = 0;         // reset for next graph replay
        float v[13];                       // entry e = tid; 0..127 b0, 128..255 b1
        const float* pp = &g_part[tid * 13];
        #pragma unroll
        for (int j = 0; j < 13; ++j) v[j] = pp[j];
        #pragma unroll
        for (int off = 16; off; off >>= 1)
            #pragma unroll
            for (int j = 0; j < 13; ++j)
                v[j] += __shfl_down_sync(0xffffffffu, v[j], off);
        if (lane == 0) {
            #pragma unroll
            for (int j = 0; j < 13; ++j) red[wy * 13 + j] = v[j];
        }
        __syncthreads();
        if (tid == 0) {
            float J1 = 0.f, J2t = 0.f;
            #pragma unroll
            for (int b2 = 0; b2 < 2; ++b2) {
                float s[13];
                #pragma unroll
                for (int j = 0; j < 13; ++j)
                    s[j] = red[(b2 * 4 + 0) * 13 + j] + red[(b2 * 4 + 1) * 13 + j] +
                           red[(b2 * 4 + 2) * 13 + j] + red[(b2 * 4 + 3) * 13 + j];
                #pragma unroll
                for (int k = 0; k < 4; ++k)
                    J1 += s[k] - s[4 + k] * s[4 + k] / s[8 + k];
                J2t += s[12];
            }
            out[0] = (J1 + 0.0008f * J2t) * (1.0f / (2.0f * (float)NVOX));
        }
    }
}

extern "C" void kernel_launch(void* const* d_in, const int* in_sizes, int n_in,
                              void* d_out, int out_size) {
    const float* yp  = (const float*)d_in[0];  // y_pred [2,4,128,128,128] f32
    const float* img = (const float*)d_in[1];  // image  [2,1,128,128,128] f32
    float* out = (float*)d_out;                // scalar f32

    cudaFuncSetAttribute(rfcm, cudaFuncAttributeMaxDynamicSharedMemorySize,
                         SMEM_BYTES);
    rfcm<<<dim3(GYB, GZB, 2), dim3(32, TY), SMEM_BYTES>>>(yp, img, out);
}